// round 1
// baseline (speedup 1.0000x reference)
#include <cuda_runtime.h>

#define M 512
#define KMAX 131072
#define PASS_GRID 608   // 4 CTAs per SM on 152 SMs

// Scratch (allocation-free rule: __device__ globals)
__device__ float    g_t[KMAX];    // t_k, then e_k, then w_k (in place)
__device__ float    g_v1[M];
__device__ float    g_v2[M];
__device__ float    g_colsum[M];
__device__ float    g_scal[4];    // [0]=c1+c2, [1]=C, [2]=Z
__device__ unsigned g_maxbits;

// ---------------------------------------------------------------------------
// Prep: v1 = W^T a1, v2 = W^T a2, c12 = b.a1 + b.a2 ; zero scratch + out
// grid = 17 blocks x 256 threads
// ---------------------------------------------------------------------------
__global__ __launch_bounds__(256) void mhi_prep(const float* __restrict__ W,
                                                const float* __restrict__ b,
                                                const float* __restrict__ a,
                                                float* __restrict__ out) {
    if (blockIdx.x < 16) {
        int j0   = blockIdx.x * 32;
        int lane = threadIdx.x & 31;
        int w    = threadIdx.x >> 5;    // 8 warps
        int j    = j0 + lane;
        float s1 = 0.f, s2 = 0.f;
        for (int i = w; i < M; i += 8) {
            float wv = W[i * M + j];    // lanes -> consecutive columns: coalesced
            s1 += wv * a[i];
            s2 += wv * a[M + i];
        }
        __shared__ float sm1[8][32], sm2[8][32];
        sm1[w][lane] = s1; sm2[w][lane] = s2;
        __syncthreads();
        if (w == 0) {
            float t1 = 0.f, t2 = 0.f;
            #pragma unroll
            for (int q = 0; q < 8; q++) { t1 += sm1[q][lane]; t2 += sm2[q][lane]; }
            g_v1[j] = t1; g_v2[j] = t2;
        }
        if (threadIdx.x < 32) {
            g_colsum[j0 + threadIdx.x] = 0.f;
            out[j0 + threadIdx.x]      = 0.f;   // d_out is poisoned: must zero
        }
    } else {
        int t = threadIdx.x;
        float p1 = 0.f, p2 = 0.f;
        for (int i = t; i < M; i += 256) {
            p1 += b[i] * a[i];
            p2 += b[i] * a[M + i];
        }
        __shared__ float r1[256], r2[256];
        r1[t] = p1; r2[t] = p2;
        __syncthreads();
        for (int s = 128; s > 0; s >>= 1) {
            if (t < s) { r1[t] += r1[t + s]; r2[t] += r2[t + s]; }
            __syncthreads();
        }
        if (t == 0) {
            g_scal[0] = r1[0] + r2[0];  // c1 + c2
            g_scal[2] = 0.f;            // Z
            g_maxbits = 0u;             // e >= 0 so uint-ordered max works
        }
    }
}

// ---------------------------------------------------------------------------
// Pass 1: t_k = x_k . v1 ; colsum[j] += x[k][j].  Warp-per-row, float4.
// ---------------------------------------------------------------------------
__global__ __launch_bounds__(256) void mhi_pass1(const float* __restrict__ x, int K) {
    __shared__ float4 sv[M / 4];
    __shared__ float  scol[M];
    int tid = threadIdx.x;
    if (tid < M / 4) sv[tid] = reinterpret_cast<const float4*>(g_v1)[tid];
    for (int j = tid; j < M; j += 256) scol[j] = 0.f;
    __syncthreads();

    int lane = tid & 31, w = tid >> 5;
    // v is loop-invariant: hoist into registers
    float4 v0 = sv[lane], v1 = sv[lane + 32], v2 = sv[lane + 64], v3 = sv[lane + 96];

    float4 a0 = {0,0,0,0}, a1 = a0, a2 = a0, a3 = a0;
    int gw = blockIdx.x * 8 + w;
    int nw = gridDim.x * 8;
    for (int k = gw; k < K; k += nw) {
        const float4* row = reinterpret_cast<const float4*>(x + (size_t)k * M);
        float4 x0 = row[lane], x1 = row[lane + 32], x2 = row[lane + 64], x3 = row[lane + 96];
        float d = x0.x*v0.x + x0.y*v0.y + x0.z*v0.z + x0.w*v0.w
                + x1.x*v1.x + x1.y*v1.y + x1.z*v1.z + x1.w*v1.w
                + x2.x*v2.x + x2.y*v2.y + x2.z*v2.z + x2.w*v2.w
                + x3.x*v3.x + x3.y*v3.y + x3.z*v3.z + x3.w*v3.w;
        #pragma unroll
        for (int o = 16; o; o >>= 1) d += __shfl_xor_sync(0xFFFFFFFFu, d, o);
        if (lane == 0) g_t[k] = d;
        a0.x += x0.x; a0.y += x0.y; a0.z += x0.z; a0.w += x0.w;
        a1.x += x1.x; a1.y += x1.y; a1.z += x1.z; a1.w += x1.w;
        a2.x += x2.x; a2.y += x2.y; a2.z += x2.z; a2.w += x2.w;
        a3.x += x3.x; a3.y += x3.y; a3.z += x3.z; a3.w += x3.w;
    }
    int c = 4 * lane;
    atomicAdd(&scol[c + 0],       a0.x); atomicAdd(&scol[c + 1],       a0.y);
    atomicAdd(&scol[c + 2],       a0.z); atomicAdd(&scol[c + 3],       a0.w);
    atomicAdd(&scol[128 + c + 0], a1.x); atomicAdd(&scol[128 + c + 1], a1.y);
    atomicAdd(&scol[128 + c + 2], a1.z); atomicAdd(&scol[128 + c + 3], a1.w);
    atomicAdd(&scol[256 + c + 0], a2.x); atomicAdd(&scol[256 + c + 1], a2.y);
    atomicAdd(&scol[256 + c + 2], a2.z); atomicAdd(&scol[256 + c + 3], a2.w);
    atomicAdd(&scol[384 + c + 0], a3.x); atomicAdd(&scol[384 + c + 1], a3.y);
    atomicAdd(&scol[384 + c + 2], a3.z); atomicAdd(&scol[384 + c + 3], a3.w);
    __syncthreads();
    for (int j = tid; j < M; j += 256) atomicAdd(&g_colsum[j], scol[j]);
}

// ---------------------------------------------------------------------------
// C = c1+c2 + (colsum/K).v2  (1 block x 512)
// ---------------------------------------------------------------------------
__global__ __launch_bounds__(512) void mhi_computeC(int K) {
    int t = threadIdx.x;
    __shared__ float r[512];
    r[t] = (g_colsum[t] * (1.0f / (float)K)) * g_v2[t];
    __syncthreads();
    for (int s = 256; s > 0; s >>= 1) {
        if (t < s) r[t] += r[t + s];
        __syncthreads();
    }
    if (t == 0) g_scal[1] = g_scal[0] + r[0];
}

// ---------------------------------------------------------------------------
// e = relu(t + C), in-place; global max via per-block reduce + atomicMax
// ---------------------------------------------------------------------------
__global__ __launch_bounds__(256) void mhi_emax(int K) {
    int i = blockIdx.x * 256 + threadIdx.x;
    float C = g_scal[1];
    float e = 0.f;
    if (i < K) {
        e = fmaxf(g_t[i] + C, 0.f);
        g_t[i] = e;
    }
    #pragma unroll
    for (int o = 16; o; o >>= 1) e = fmaxf(e, __shfl_xor_sync(0xFFFFFFFFu, e, o));
    __shared__ float sm[8];
    if ((threadIdx.x & 31) == 0) sm[threadIdx.x >> 5] = e;
    __syncthreads();
    if (threadIdx.x == 0) {
        float m = sm[0];
        #pragma unroll
        for (int q = 1; q < 8; q++) m = fmaxf(m, sm[q]);
        atomicMax(&g_maxbits, __float_as_uint(m));
    }
}

// ---------------------------------------------------------------------------
// w = exp(e - m), in-place; Z = sum(w)
// ---------------------------------------------------------------------------
__global__ __launch_bounds__(256) void mhi_sumexp(int K) {
    int i = blockIdx.x * 256 + threadIdx.x;
    float m = __uint_as_float(g_maxbits);
    float wv = 0.f;
    if (i < K) { wv = __expf(g_t[i] - m); g_t[i] = wv; }
    #pragma unroll
    for (int o = 16; o; o >>= 1) wv += __shfl_xor_sync(0xFFFFFFFFu, wv, o);
    __shared__ float sm[8];
    if ((threadIdx.x & 31) == 0) sm[threadIdx.x >> 5] = wv;
    __syncthreads();
    if (threadIdx.x == 0) {
        float s = 0.f;
        #pragma unroll
        for (int q = 0; q < 8; q++) s += sm[q];
        atomicAdd(&g_scal[2], s);
    }
}

// ---------------------------------------------------------------------------
// Pass 2: out[j] = (1/Z) * sum_k w_k x[k][j].  Warp-per-row, float4.
// ---------------------------------------------------------------------------
__global__ __launch_bounds__(256) void mhi_pass2(const float* __restrict__ x,
                                                 float* __restrict__ out, int K) {
    __shared__ float scol[M];
    int tid = threadIdx.x;
    for (int j = tid; j < M; j += 256) scol[j] = 0.f;
    __syncthreads();
    float invZ = 1.0f / g_scal[2];
    int lane = tid & 31, w = tid >> 5;
    float4 a0 = {0,0,0,0}, a1 = a0, a2 = a0, a3 = a0;
    int gw = blockIdx.x * 8 + w;
    int nw = gridDim.x * 8;
    for (int k = gw; k < K; k += nw) {
        float wk = g_t[k];
        const float4* row = reinterpret_cast<const float4*>(x + (size_t)k * M);
        float4 x0 = row[lane], x1 = row[lane + 32], x2 = row[lane + 64], x3 = row[lane + 96];
        a0.x += wk * x0.x; a0.y += wk * x0.y; a0.z += wk * x0.z; a0.w += wk * x0.w;
        a1.x += wk * x1.x; a1.y += wk * x1.y; a1.z += wk * x1.z; a1.w += wk * x1.w;
        a2.x += wk * x2.x; a2.y += wk * x2.y; a2.z += wk * x2.z; a2.w += wk * x2.w;
        a3.x += wk * x3.x; a3.y += wk * x3.y; a3.z += wk * x3.z; a3.w += wk * x3.w;
    }
    int c = 4 * lane;
    atomicAdd(&scol[c + 0],       a0.x); atomicAdd(&scol[c + 1],       a0.y);
    atomicAdd(&scol[c + 2],       a0.z); atomicAdd(&scol[c + 3],       a0.w);
    atomicAdd(&scol[128 + c + 0], a1.x); atomicAdd(&scol[128 + c + 1], a1.y);
    atomicAdd(&scol[128 + c + 2], a1.z); atomicAdd(&scol[128 + c + 3], a1.w);
    atomicAdd(&scol[256 + c + 0], a2.x); atomicAdd(&scol[256 + c + 1], a2.y);
    atomicAdd(&scol[256 + c + 2], a2.z); atomicAdd(&scol[256 + c + 3], a2.w);
    atomicAdd(&scol[384 + c + 0], a3.x); atomicAdd(&scol[384 + c + 1], a3.y);
    atomicAdd(&scol[384 + c + 2], a3.z); atomicAdd(&scol[384 + c + 3], a3.w);
    __syncthreads();
    for (int j = tid; j < M; j += 256) atomicAdd(&out[j], scol[j] * invZ);
}

// ---------------------------------------------------------------------------
extern "C" void kernel_launch(void* const* d_in, const int* in_sizes, int n_in,
                              void* d_out, int out_size) {
    const float* x = (const float*)d_in[0];   // [K, 512]
    const float* W = (const float*)d_in[1];   // [512, 512]
    const float* b = (const float*)d_in[2];   // [512]
    const float* a = (const float*)d_in[3];   // [1024]
    float* out = (float*)d_out;               // [512]
    int K = in_sizes[0] / M;

    mhi_prep<<<17, 256>>>(W, b, a, out);
    mhi_pass1<<<PASS_GRID, 256>>>(x, K);
    mhi_computeC<<<1, 512>>>(K);
    int g = (K + 255) / 256;
    mhi_emax<<<g, 256>>>(K);
    mhi_sumexp<<<g, 256>>>(K);
    mhi_pass2<<<PASS_GRID, 256>>>(x, out, K);
}

// round 2
// speedup vs baseline: 1.0439x; 1.0439x over previous
#include <cuda_runtime.h>

#define M 512
#define KMAX 131072
#define PASS_GRID 608   // ~4 CTAs per SM on 152 SMs

// Scratch (allocation-free rule: __device__ globals)
__device__ float    g_t[KMAX];     // t_k
__device__ float    g_v1[M];
__device__ float    g_v2[M];
__device__ float    g_colsum[M];
__device__ float    g_scal[4];     // [0]=c1+c2, [1]=C, [2]=Z
__device__ unsigned g_cnt1;        // pass1 completion counter
__device__ unsigned g_cnt2;        // pass2 completion counter

// ---------------------------------------------------------------------------
// Prep: v1 = W^T a1, v2 = W^T a2, c12 = b.a1 + b.a2 ; zero scratch + out
// grid = 17 blocks x 256 threads
// ---------------------------------------------------------------------------
__global__ __launch_bounds__(256) void mhi_prep(const float* __restrict__ W,
                                                const float* __restrict__ b,
                                                const float* __restrict__ a,
                                                float* __restrict__ out) {
    if (blockIdx.x < 16) {
        int j0   = blockIdx.x * 32;
        int lane = threadIdx.x & 31;
        int w    = threadIdx.x >> 5;    // 8 warps
        int j    = j0 + lane;
        float s1 = 0.f, s2 = 0.f;
        for (int i = w; i < M; i += 8) {
            float wv = W[i * M + j];    // lanes -> consecutive columns: coalesced
            s1 += wv * a[i];
            s2 += wv * a[M + i];
        }
        __shared__ float sm1[8][32], sm2[8][32];
        sm1[w][lane] = s1; sm2[w][lane] = s2;
        __syncthreads();
        if (w == 0) {
            float t1 = 0.f, t2 = 0.f;
            #pragma unroll
            for (int q = 0; q < 8; q++) { t1 += sm1[q][lane]; t2 += sm2[q][lane]; }
            g_v1[j] = t1; g_v2[j] = t2;
        }
        if (threadIdx.x < 32) {
            g_colsum[j0 + threadIdx.x] = 0.f;
            out[j0 + threadIdx.x]      = 0.f;   // d_out is poisoned: must zero
        }
    } else {
        int t = threadIdx.x;
        float p1 = 0.f, p2 = 0.f;
        for (int i = t; i < M; i += 256) {
            p1 += b[i] * a[i];
            p2 += b[i] * a[M + i];
        }
        __shared__ float r1[256], r2[256];
        r1[t] = p1; r2[t] = p2;
        __syncthreads();
        for (int s = 128; s > 0; s >>= 1) {
            if (t < s) { r1[t] += r1[t + s]; r2[t] += r2[t + s]; }
            __syncthreads();
        }
        if (t == 0) {
            g_scal[0] = r1[0] + r2[0];  // c1 + c2
            g_scal[2] = 0.f;            // Z
            g_cnt1 = 0u;                // re-zero every replay (graph determinism)
            g_cnt2 = 0u;
        }
    }
}

// ---------------------------------------------------------------------------
// Pass 1: t_k = x_k . v1 ; colsum[j] += x[k][j].
// Warp-per-row, float4, 2 rows per iteration (8 LDG.128 in flight / warp).
// Last CTA computes C = c1+c2 + mean(x).v2 in-place (no extra launch).
// ---------------------------------------------------------------------------
__global__ __launch_bounds__(256) void mhi_pass1(const float* __restrict__ x, int K) {
    __shared__ float4 sv[M / 4];
    __shared__ float  scol[M];
    int tid = threadIdx.x;
    if (tid < M / 4) sv[tid] = reinterpret_cast<const float4*>(g_v1)[tid];
    for (int j = tid; j < M; j += 256) scol[j] = 0.f;
    __syncthreads();

    int lane = tid & 31, w = tid >> 5;
    float4 v0 = sv[lane], v1 = sv[lane + 32], v2 = sv[lane + 64], v3 = sv[lane + 96];

    float4 a0 = {0,0,0,0}, a1 = a0, a2 = a0, a3 = a0;
    int gw = blockIdx.x * 8 + w;
    int nw = gridDim.x * 8;
    for (int k = gw * 2; k < K; k += nw * 2) {
        const float4* rA = reinterpret_cast<const float4*>(x + (size_t)k * M);
        float4 x0 = rA[lane], x1 = rA[lane + 32], x2 = rA[lane + 64], x3 = rA[lane + 96];
        bool hasB = (k + 1) < K;
        const float4* rB = reinterpret_cast<const float4*>(x + (size_t)(hasB ? k + 1 : k) * M);
        float4 y0 = rB[lane], y1 = rB[lane + 32], y2 = rB[lane + 64], y3 = rB[lane + 96];

        float dA = x0.x*v0.x + x0.y*v0.y + x0.z*v0.z + x0.w*v0.w
                 + x1.x*v1.x + x1.y*v1.y + x1.z*v1.z + x1.w*v1.w
                 + x2.x*v2.x + x2.y*v2.y + x2.z*v2.z + x2.w*v2.w
                 + x3.x*v3.x + x3.y*v3.y + x3.z*v3.z + x3.w*v3.w;
        float dB = y0.x*v0.x + y0.y*v0.y + y0.z*v0.z + y0.w*v0.w
                 + y1.x*v1.x + y1.y*v1.y + y1.z*v1.z + y1.w*v1.w
                 + y2.x*v2.x + y2.y*v2.y + y2.z*v2.z + y2.w*v2.w
                 + y3.x*v3.x + y3.y*v3.y + y3.z*v3.z + y3.w*v3.w;
        #pragma unroll
        for (int o = 16; o; o >>= 1) {
            dA += __shfl_xor_sync(0xFFFFFFFFu, dA, o);
            dB += __shfl_xor_sync(0xFFFFFFFFu, dB, o);
        }
        if (lane == 0) {
            g_t[k] = dA;
            if (hasB) g_t[k + 1] = dB;
        }
        a0.x += x0.x; a0.y += x0.y; a0.z += x0.z; a0.w += x0.w;
        a1.x += x1.x; a1.y += x1.y; a1.z += x1.z; a1.w += x1.w;
        a2.x += x2.x; a2.y += x2.y; a2.z += x2.z; a2.w += x2.w;
        a3.x += x3.x; a3.y += x3.y; a3.z += x3.z; a3.w += x3.w;
        if (hasB) {
            a0.x += y0.x; a0.y += y0.y; a0.z += y0.z; a0.w += y0.w;
            a1.x += y1.x; a1.y += y1.y; a1.z += y1.z; a1.w += y1.w;
            a2.x += y2.x; a2.y += y2.y; a2.z += y2.z; a2.w += y2.w;
            a3.x += y3.x; a3.y += y3.y; a3.z += y3.z; a3.w += y3.w;
        }
    }
    int c = 4 * lane;
    atomicAdd(&scol[c + 0],       a0.x); atomicAdd(&scol[c + 1],       a0.y);
    atomicAdd(&scol[c + 2],       a0.z); atomicAdd(&scol[c + 3],       a0.w);
    atomicAdd(&scol[128 + c + 0], a1.x); atomicAdd(&scol[128 + c + 1], a1.y);
    atomicAdd(&scol[128 + c + 2], a1.z); atomicAdd(&scol[128 + c + 3], a1.w);
    atomicAdd(&scol[256 + c + 0], a2.x); atomicAdd(&scol[256 + c + 1], a2.y);
    atomicAdd(&scol[256 + c + 2], a2.z); atomicAdd(&scol[256 + c + 3], a2.w);
    atomicAdd(&scol[384 + c + 0], a3.x); atomicAdd(&scol[384 + c + 1], a3.y);
    atomicAdd(&scol[384 + c + 2], a3.z); atomicAdd(&scol[384 + c + 3], a3.w);
    __syncthreads();
    for (int j = tid; j < M; j += 256) atomicAdd(&g_colsum[j], scol[j]);

    // Last CTA computes C (replaces the mhi_computeC launch)
    __shared__ bool isLast;
    __threadfence();
    __syncthreads();
    if (tid == 0) isLast = (atomicAdd(&g_cnt1, 1u) == gridDim.x - 1);
    __syncthreads();
    if (isLast) {
        float p = 0.f;
        for (int j = tid; j < M; j += 256) p += g_colsum[j] * g_v2[j];
        #pragma unroll
        for (int o = 16; o; o >>= 1) p += __shfl_xor_sync(0xFFFFFFFFu, p, o);
        __shared__ float sp[8];
        if (lane == 0) sp[w] = p;
        __syncthreads();
        if (tid == 0) {
            float s = 0.f;
            #pragma unroll
            for (int q = 0; q < 8; q++) s += sp[q];
            g_scal[1] = g_scal[0] + s * (1.0f / (float)K);
        }
    }
}

// ---------------------------------------------------------------------------
// Pass 2: w_k = exp(relu(t_k + C)) computed inline (softmax is shift-
// invariant; e in [0,~6] so no max subtraction needed).
// out[j] (unnormalized) += sum_k w_k x[k][j]; Z += sum w_k.
// Last CTA divides out by Z.
// ---------------------------------------------------------------------------
__global__ __launch_bounds__(256) void mhi_pass2(const float* __restrict__ x,
                                                 float* __restrict__ out, int K) {
    __shared__ float scol[M];
    int tid = threadIdx.x;
    for (int j = tid; j < M; j += 256) scol[j] = 0.f;
    __syncthreads();
    float C = g_scal[1];
    int lane = tid & 31, w = tid >> 5;
    float4 a0 = {0,0,0,0}, a1 = a0, a2 = a0, a3 = a0;
    float zloc = 0.f;
    int gw = blockIdx.x * 8 + w;
    int nw = gridDim.x * 8;
    for (int k = gw * 2; k < K; k += nw * 2) {
        bool hasB = (k + 1) < K;
        float wA = __expf(fmaxf(g_t[k] + C, 0.f));
        float wB = hasB ? __expf(fmaxf(g_t[k + 1] + C, 0.f)) : 0.f;
        const float4* rA = reinterpret_cast<const float4*>(x + (size_t)k * M);
        float4 x0 = rA[lane], x1 = rA[lane + 32], x2 = rA[lane + 64], x3 = rA[lane + 96];
        const float4* rB = reinterpret_cast<const float4*>(x + (size_t)(hasB ? k + 1 : k) * M);
        float4 y0 = rB[lane], y1 = rB[lane + 32], y2 = rB[lane + 64], y3 = rB[lane + 96];
        a0.x += wA*x0.x + wB*y0.x; a0.y += wA*x0.y + wB*y0.y;
        a0.z += wA*x0.z + wB*y0.z; a0.w += wA*x0.w + wB*y0.w;
        a1.x += wA*x1.x + wB*y1.x; a1.y += wA*x1.y + wB*y1.y;
        a1.z += wA*x1.z + wB*y1.z; a1.w += wA*x1.w + wB*y1.w;
        a2.x += wA*x2.x + wB*y2.x; a2.y += wA*x2.y + wB*y2.y;
        a2.z += wA*x2.z + wB*y2.z; a2.w += wA*x2.w + wB*y2.w;
        a3.x += wA*x3.x + wB*y3.x; a3.y += wA*x3.y + wB*y3.y;
        a3.z += wA*x3.z + wB*y3.z; a3.w += wA*x3.w + wB*y3.w;
        zloc += wA + wB;
    }
    // zloc is identical across lanes of the warp: take one copy per warp
    __shared__ float zw[8];
    if (lane == 0) zw[w] = zloc;

    int c = 4 * lane;
    atomicAdd(&scol[c + 0],       a0.x); atomicAdd(&scol[c + 1],       a0.y);
    atomicAdd(&scol[c + 2],       a0.z); atomicAdd(&scol[c + 3],       a0.w);
    atomicAdd(&scol[128 + c + 0], a1.x); atomicAdd(&scol[128 + c + 1], a1.y);
    atomicAdd(&scol[128 + c + 2], a1.z); atomicAdd(&scol[128 + c + 3], a1.w);
    atomicAdd(&scol[256 + c + 0], a2.x); atomicAdd(&scol[256 + c + 1], a2.y);
    atomicAdd(&scol[256 + c + 2], a2.z); atomicAdd(&scol[256 + c + 3], a2.w);
    atomicAdd(&scol[384 + c + 0], a3.x); atomicAdd(&scol[384 + c + 1], a3.y);
    atomicAdd(&scol[384 + c + 2], a3.z); atomicAdd(&scol[384 + c + 3], a3.w);
    __syncthreads();
    if (tid == 0) {
        float z = 0.f;
        #pragma unroll
        for (int q = 0; q < 8; q++) z += zw[q];
        atomicAdd(&g_scal[2], z);
    }
    for (int j = tid; j < M; j += 256) atomicAdd(&out[j], scol[j]);

    // Last CTA normalizes by Z (replaces a separate launch)
    __shared__ bool isLast;
    __threadfence();
    __syncthreads();
    if (tid == 0) isLast = (atomicAdd(&g_cnt2, 1u) == gridDim.x - 1);
    __syncthreads();
    if (isLast) {
        float invZ = 1.0f / g_scal[2];
        for (int j = tid; j < M; j += 256) out[j] *= invZ;
    }
}

// ---------------------------------------------------------------------------
extern "C" void kernel_launch(void* const* d_in, const int* in_sizes, int n_in,
                              void* d_out, int out_size) {
    const float* x = (const float*)d_in[0];   // [K, 512]
    const float* W = (const float*)d_in[1];   // [512, 512]
    const float* b = (const float*)d_in[2];   // [512]
    const float* a = (const float*)d_in[3];   // [1024]
    float* out = (float*)d_out;               // [512]
    int K = in_sizes[0] / M;

    mhi_prep<<<17, 256>>>(W, b, a, out);
    mhi_pass1<<<PASS_GRID, 256>>>(x, K);
    mhi_pass2<<<PASS_GRID, 256>>>(x, out, K);
}

// round 3
// speedup vs baseline: 1.1860x; 1.1361x over previous
#include <cuda_runtime.h>

#define M 512
#define KMAX 131072
#define PASS_GRID 608   // ~4 CTAs per SM on 152 SMs

// Scratch (allocation-free rule: __device__ globals; zero-initialized at load).
// Cleanup-at-end protocol: every accumulated variable is re-zeroed by the last
// CTA that consumes it, so each graph replay starts from a clean state.
__device__ float    g_t[KMAX];     // t_k
__device__ float    g_v1[M];       // W^T a1   (atomic accum; zeroed by pass1 last CTA)
__device__ float    g_v2[M];       // W^T a2   (atomic accum; zeroed by pass1 last CTA)
__device__ float    g_colsum[M];   // column sums of x (zeroed by pass1 last CTA)
__device__ float    g_scal[4];     // [0]=c1+c2 (overwritten), [1]=C (overwritten), [2]=Z (zeroed)
__device__ unsigned g_cnt1;        // pass1 completion counter (zeroed by its last CTA)
__device__ unsigned g_cnt2;        // pass2 completion counter (zeroed by its last CTA)

// ---------------------------------------------------------------------------
// Prep: v1 += W^T a1, v2 += W^T a2 (atomics into zeroed globals);
//       c12 = b.a1 + b.a2 ; zero out.
// Blocks 0..63: 8 contiguous rows of W each, fully-coalesced float4 reads.
// Block 64: b-dot + zero out.
// ---------------------------------------------------------------------------
__global__ __launch_bounds__(256) void mhi_prep(const float* __restrict__ W,
                                                const float* __restrict__ b,
                                                const float* __restrict__ a,
                                                float* __restrict__ out) {
    if (blockIdx.x < 64) {
        int i0 = blockIdx.x * 8;
        int c4 = threadIdx.x & 127;   // float4 column index (covers cols 4c4..4c4+3)
        int rg = threadIdx.x >> 7;    // row group 0/1
        const float4* W4 = reinterpret_cast<const float4*>(W);
        float4 s1 = {0,0,0,0}, s2 = {0,0,0,0};
        #pragma unroll
        for (int rr = 0; rr < 4; rr++) {
            int row = i0 + rg + rr * 2;
            float4 w4 = W4[row * 128 + c4];
            float A1 = __ldg(a + row);
            float A2 = __ldg(a + M + row);
            s1.x += A1 * w4.x; s1.y += A1 * w4.y; s1.z += A1 * w4.z; s1.w += A1 * w4.w;
            s2.x += A2 * w4.x; s2.y += A2 * w4.y; s2.z += A2 * w4.z; s2.w += A2 * w4.w;
        }
        int j = c4 * 4;
        atomicAdd(&g_v1[j + 0], s1.x); atomicAdd(&g_v1[j + 1], s1.y);
        atomicAdd(&g_v1[j + 2], s1.z); atomicAdd(&g_v1[j + 3], s1.w);
        atomicAdd(&g_v2[j + 0], s2.x); atomicAdd(&g_v2[j + 1], s2.y);
        atomicAdd(&g_v2[j + 2], s2.z); atomicAdd(&g_v2[j + 3], s2.w);
    } else {
        int t = threadIdx.x;
        out[t]       = 0.f;           // d_out is poisoned: must zero before pass2 atomics
        out[t + 256] = 0.f;
        float p1 = 0.f, p2 = 0.f;
        for (int i = t; i < M; i += 256) {
            p1 += b[i] * a[i];
            p2 += b[i] * a[M + i];
        }
        __shared__ float r1[256], r2[256];
        r1[t] = p1; r2[t] = p2;
        __syncthreads();
        for (int s = 128; s > 0; s >>= 1) {
            if (t < s) { r1[t] += r1[t + s]; r2[t] += r2[t + s]; }
            __syncthreads();
        }
        if (t == 0) g_scal[0] = r1[0] + r2[0];  // c1 + c2
    }
}

// ---------------------------------------------------------------------------
// Pass 1 (ascending bands): t_k = x_k . v1 ; colsum[j] += x[k][j].
// Warp-per-row, float4, 2 rows per iteration.
// Last CTA computes C = c1+c2 + mean(x).v2 and zeroes the accumulators.
// ---------------------------------------------------------------------------
__global__ __launch_bounds__(256) void mhi_pass1(const float* __restrict__ x, int K) {
    __shared__ float4 sv[M / 4];
    __shared__ float  scol[M];
    int tid = threadIdx.x;
    if (tid < M / 4) sv[tid] = reinterpret_cast<const float4*>(g_v1)[tid];
    for (int j = tid; j < M; j += 256) scol[j] = 0.f;
    __syncthreads();

    int lane = tid & 31, w = tid >> 5;
    float4 v0 = sv[lane], v1 = sv[lane + 32], v2 = sv[lane + 64], v3 = sv[lane + 96];

    float4 a0 = {0,0,0,0}, a1 = a0, a2 = a0, a3 = a0;
    int gw = blockIdx.x * 8 + w;
    int nw = gridDim.x * 8;
    for (int k = gw * 2; k < K; k += nw * 2) {
        const float4* rA = reinterpret_cast<const float4*>(x + (size_t)k * M);
        float4 x0 = rA[lane], x1 = rA[lane + 32], x2 = rA[lane + 64], x3 = rA[lane + 96];
        bool hasB = (k + 1) < K;
        const float4* rB = reinterpret_cast<const float4*>(x + (size_t)(hasB ? k + 1 : k) * M);
        float4 y0 = rB[lane], y1 = rB[lane + 32], y2 = rB[lane + 64], y3 = rB[lane + 96];

        float dA = x0.x*v0.x + x0.y*v0.y + x0.z*v0.z + x0.w*v0.w
                 + x1.x*v1.x + x1.y*v1.y + x1.z*v1.z + x1.w*v1.w
                 + x2.x*v2.x + x2.y*v2.y + x2.z*v2.z + x2.w*v2.w
                 + x3.x*v3.x + x3.y*v3.y + x3.z*v3.z + x3.w*v3.w;
        float dB = y0.x*v0.x + y0.y*v0.y + y0.z*v0.z + y0.w*v0.w
                 + y1.x*v1.x + y1.y*v1.y + y1.z*v1.z + y1.w*v1.w
                 + y2.x*v2.x + y2.y*v2.y + y2.z*v2.z + y2.w*v2.w
                 + y3.x*v3.x + y3.y*v3.y + y3.z*v3.z + y3.w*v3.w;
        #pragma unroll
        for (int o = 16; o; o >>= 1) {
            dA += __shfl_xor_sync(0xFFFFFFFFu, dA, o);
            dB += __shfl_xor_sync(0xFFFFFFFFu, dB, o);
        }
        if (lane == 0) {
            g_t[k] = dA;
            if (hasB) g_t[k + 1] = dB;
        }
        a0.x += x0.x; a0.y += x0.y; a0.z += x0.z; a0.w += x0.w;
        a1.x += x1.x; a1.y += x1.y; a1.z += x1.z; a1.w += x1.w;
        a2.x += x2.x; a2.y += x2.y; a2.z += x2.z; a2.w += x2.w;
        a3.x += x3.x; a3.y += x3.y; a3.z += x3.z; a3.w += x3.w;
        if (hasB) {
            a0.x += y0.x; a0.y += y0.y; a0.z += y0.z; a0.w += y0.w;
            a1.x += y1.x; a1.y += y1.y; a1.z += y1.z; a1.w += y1.w;
            a2.x += y2.x; a2.y += y2.y; a2.z += y2.z; a2.w += y2.w;
            a3.x += y3.x; a3.y += y3.y; a3.z += y3.z; a3.w += y3.w;
        }
    }
    int c = 4 * lane;
    atomicAdd(&scol[c + 0],       a0.x); atomicAdd(&scol[c + 1],       a0.y);
    atomicAdd(&scol[c + 2],       a0.z); atomicAdd(&scol[c + 3],       a0.w);
    atomicAdd(&scol[128 + c + 0], a1.x); atomicAdd(&scol[128 + c + 1], a1.y);
    atomicAdd(&scol[128 + c + 2], a1.z); atomicAdd(&scol[128 + c + 3], a1.w);
    atomicAdd(&scol[256 + c + 0], a2.x); atomicAdd(&scol[256 + c + 1], a2.y);
    atomicAdd(&scol[256 + c + 2], a2.z); atomicAdd(&scol[256 + c + 3], a2.w);
    atomicAdd(&scol[384 + c + 0], a3.x); atomicAdd(&scol[384 + c + 1], a3.y);
    atomicAdd(&scol[384 + c + 2], a3.z); atomicAdd(&scol[384 + c + 3], a3.w);
    __syncthreads();
    for (int j = tid; j < M; j += 256) atomicAdd(&g_colsum[j], scol[j]);

    // Last CTA: compute C, then clean up accumulators for next graph replay.
    __shared__ bool isLast;
    __threadfence();
    __syncthreads();
    if (tid == 0) isLast = (atomicAdd(&g_cnt1, 1u) == gridDim.x - 1);
    __syncthreads();
    if (isLast) {
        float p = 0.f;
        for (int j = tid; j < M; j += 256) p += g_colsum[j] * g_v2[j];
        #pragma unroll
        for (int o = 16; o; o >>= 1) p += __shfl_xor_sync(0xFFFFFFFFu, p, o);
        __shared__ float sp[8];
        if (lane == 0) sp[w] = p;
        __syncthreads();           // all reads of g_colsum/g_v2 complete
        for (int j = tid; j < M; j += 256) {
            g_colsum[j] = 0.f;
            g_v1[j] = 0.f;
            g_v2[j] = 0.f;
        }
        if (tid == 0) {
            float s = 0.f;
            #pragma unroll
            for (int q = 0; q < 8; q++) s += sp[q];
            g_scal[1] = g_scal[0] + s * (1.0f / (float)K);
            g_cnt1 = 0u;
        }
    }
}

// ---------------------------------------------------------------------------
// Pass 2 (DESCENDING bands — the top ~126MB of x is still L2-resident from
// pass1's ascending sweep): w_k = exp(relu(t_k + C)) inline (softmax is
// shift-invariant; e in [0,~6] so no max subtraction needed).
// out[j] (unnormalized) += sum_k w_k x[k][j]; Z += sum w_k.
// Last CTA divides out by Z and cleans up.
// ---------------------------------------------------------------------------
__global__ __launch_bounds__(256) void mhi_pass2(const float* __restrict__ x,
                                                 float* __restrict__ out, int K) {
    __shared__ float scol[M];
    int tid = threadIdx.x;
    for (int j = tid; j < M; j += 256) scol[j] = 0.f;
    __syncthreads();
    float C = g_scal[1];
    int lane = tid & 31, w = tid >> 5;
    float4 a0 = {0,0,0,0}, a1 = a0, a2 = a0, a3 = a0;
    float zloc = 0.f;
    int gw = blockIdx.x * 8 + w;
    int nw = gridDim.x * 8;
    int P = (K + 1) >> 1;                        // number of row pairs
    for (int p = P - 1 - gw; p >= 0; p -= nw) {  // descending
        int k = 2 * p;
        bool hasB = (k + 1) < K;
        float wA = __expf(fmaxf(g_t[k] + C, 0.f));
        float wB = hasB ? __expf(fmaxf(g_t[k + 1] + C, 0.f)) : 0.f;
        const float4* rA = reinterpret_cast<const float4*>(x + (size_t)k * M);
        float4 x0 = rA[lane], x1 = rA[lane + 32], x2 = rA[lane + 64], x3 = rA[lane + 96];
        const float4* rB = reinterpret_cast<const float4*>(x + (size_t)(hasB ? k + 1 : k) * M);
        float4 y0 = rB[lane], y1 = rB[lane + 32], y2 = rB[lane + 64], y3 = rB[lane + 96];
        a0.x += wA*x0.x + wB*y0.x; a0.y += wA*x0.y + wB*y0.y;
        a0.z += wA*x0.z + wB*y0.z; a0.w += wA*x0.w + wB*y0.w;
        a1.x += wA*x1.x + wB*y1.x; a1.y += wA*x1.y + wB*y1.y;
        a1.z += wA*x1.z + wB*y1.z; a1.w += wA*x1.w + wB*y1.w;
        a2.x += wA*x2.x + wB*y2.x; a2.y += wA*x2.y + wB*y2.y;
        a2.z += wA*x2.z + wB*y2.z; a2.w += wA*x2.w + wB*y2.w;
        a3.x += wA*x3.x + wB*y3.x; a3.y += wA*x3.y + wB*y3.y;
        a3.z += wA*x3.z + wB*y3.z; a3.w += wA*x3.w + wB*y3.w;
        zloc += wA + wB;
    }
    // zloc is identical across lanes of the warp: take one copy per warp
    __shared__ float zw[8];
    if (lane == 0) zw[w] = zloc;

    int c = 4 * lane;
    atomicAdd(&scol[c + 0],       a0.x); atomicAdd(&scol[c + 1],       a0.y);
    atomicAdd(&scol[c + 2],       a0.z); atomicAdd(&scol[c + 3],       a0.w);
    atomicAdd(&scol[128 + c + 0], a1.x); atomicAdd(&scol[128 + c + 1], a1.y);
    atomicAdd(&scol[128 + c + 2], a1.z); atomicAdd(&scol[128 + c + 3], a1.w);
    atomicAdd(&scol[256 + c + 0], a2.x); atomicAdd(&scol[256 + c + 1], a2.y);
    atomicAdd(&scol[256 + c + 2], a2.z); atomicAdd(&scol[256 + c + 3], a2.w);
    atomicAdd(&scol[384 + c + 0], a3.x); atomicAdd(&scol[384 + c + 1], a3.y);
    atomicAdd(&scol[384 + c + 2], a3.z); atomicAdd(&scol[384 + c + 3], a3.w);
    __syncthreads();
    if (tid == 0) {
        float z = 0.f;
        #pragma unroll
        for (int q = 0; q < 8; q++) z += zw[q];
        atomicAdd(&g_scal[2], z);
    }
    for (int j = tid; j < M; j += 256) atomicAdd(&out[j], scol[j]);

    // Last CTA normalizes by Z, then cleans up for the next graph replay.
    __shared__ bool isLast;
    __threadfence();
    __syncthreads();
    if (tid == 0) isLast = (atomicAdd(&g_cnt2, 1u) == gridDim.x - 1);
    __syncthreads();
    if (isLast) {
        float invZ = 1.0f / g_scal[2];
        for (int j = tid; j < M; j += 256) out[j] *= invZ;
        if (tid == 0) { g_scal[2] = 0.f; g_cnt2 = 0u; }
    }
}

// ---------------------------------------------------------------------------
extern "C" void kernel_launch(void* const* d_in, const int* in_sizes, int n_in,
                              void* d_out, int out_size) {
    const float* x = (const float*)d_in[0];   // [K, 512]
    const float* W = (const float*)d_in[1];   // [512, 512]
    const float* b = (const float*)d_in[2];   // [512]
    const float* a = (const float*)d_in[3];   // [1024]
    float* out = (float*)d_out;               // [512]
    int K = in_sizes[0] / M;

    mhi_prep<<<65, 256>>>(W, b, a, out);
    mhi_pass1<<<PASS_GRID, 256>>>(x, K);
    mhi_pass2<<<PASS_GRID, 256>>>(x, out, K);
}